// round 12
// baseline (speedup 1.0000x reference)
#include <cuda_runtime.h>
#include <cstdint>

#define N_WL 262144

// Persistent scratch (no allocations allowed)
__device__ float g_coef[96];   // [0:64) = m2, [64:96) = h

__device__ const float LNU0[10]  = {254.f, 280.f, 310.f, 940.f, 1130.f, 1380.f, 1400.f, 1600.f, 2000.f, 2700.f};
__device__ const float LSTR[10]  = {1.15e-17f, 5e-18f, 1.9e-19f, 2.5e-23f, 8.2e-24f, 1.8e-22f, 3.5e-25f, 7.8e-26f, 4.2e-24f, 1.2e-24f};
__device__ const float LWID[10]  = {2.0f, 3.0f, 2.5f, 3.0f, 2.5f, 4.0f, 3.0f, 2.5f, 4.0f, 3.5f};
__device__ const float LTE[10]   = {0.05f, 0.04f, 0.03f, 0.4f, 0.35f, 0.45f, 0.5f, 0.48f, 0.52f, 0.49f};
__device__ const float LMASS[10] = {48.f, 48.f, 48.f, 18.f, 18.f, 18.f, 44.f, 44.f, 44.f, 44.f};

// Voigt profile contribution for one line (prep kernel only).
__device__ __forceinline__ float voigt_line(float wl, float4 L) {
    float x  = (wl - L.x) * L.y;
    float y  = L.z;
    float ax = fabsf(x);
    float s  = ax + y;
    float w;
    if (s >= 15.0f) {
        float t2r = y * y - x * x;
        float t2i = -2.0f * x * y;
        float dr  = 0.5f + t2r;
        float di  = t2i;
        float nr  = 0.5641896f * y;
        float ni  = 0.5641896f * (-x);
        w = (nr * dr + ni * di) / (dr * dr + di * di);
    } else if (ax >= 5.5f) {
        float tr = y, ti = -x;
        float ur = y * y - x * x;
        float ui = -2.0f * x * y;
        float ar = 1.410474f + 0.5641896f * ur;
        float ai = 0.5641896f * ui;
        float nr = tr * ar - ti * ai;
        float ni = tr * ai + ti * ar;
        float u2r = ur * ur - ui * ui;
        float u2i = 2.0f * ur * ui;
        float dr = 0.75f + 3.0f * ur + u2r;
        float di = 3.0f * ui + u2i;
        w = (nr * dr + ni * di) / (dr * dr + di * di);
    } else {
        float xx = x * x;
        w = expf(-xx) * cosf(2.0f * x * y) * 0.5641896f
          + (2.0f * y / 3.14159265358979f) * sinf(xx) / (xx + y * y + 1e-10f);
    }
    return L.w * w;
}

__device__ __forceinline__ float softplus_f(float z) {
    return fmaxf(z, 0.0f) + log1pf(expf(-fabsf(z)));
}
__device__ __forceinline__ float silu_f(float z) {
    return z / (1.0f + expf(-z));
}
__device__ __forceinline__ float tanh_approx(float z) {
    float r;
    asm("tanh.approx.f32 %0, %1;" : "=f"(r) : "f"(z));
    return r;
}

__device__ __forceinline__ uint32_t smem_u32(const void* p) {
    uint32_t a;
    asm("{ .reg .u64 t; cvta.to.shared.u64 t, %1; cvt.u32.u64 %0, t; }" : "=r"(a) : "l"(p));
    return a;
}
__device__ __forceinline__ void cp_async16(uint32_t dst, const void* src) {
    asm volatile("cp.async.cg.shared.global [%0], [%1], 16;" :: "r"(dst), "l"(src) : "memory");
}

// ---------------------------------------------------------------------------
// Kernel A: tiny prep — h[32], cross[:8], m2[64] -> g_coef[96]
// ---------------------------------------------------------------------------
__global__ void prep_kernel(
    const float* __restrict__ wl,
    const float* __restrict__ Tp,  const float* __restrict__ Pp,
    const float* __restrict__ o3p, const float* __restrict__ h2op, const float* __restrict__ co2p,
    const float* __restrict__ mix_w1,  const float* __restrict__ mix_b1,
    const float* __restrict__ mix_w2,  const float* __restrict__ mix_b2,
    const float* __restrict__ cont_w1, const float* __restrict__ cont_b1,
    const float* __restrict__ cont_w2, const float* __restrict__ cont_b2)
{
    __shared__ float4 s_line[10];
    __shared__ float  s_h[32];
    __shared__ float  s_feat[10];
    __shared__ float  s_m1[64];

    const int t = threadIdx.x;   // 64 threads
    const float T = Tp[0];
    const float P = Pp[0];

    if (t < 10) {
        float conc = (t < 3) ? o3p[0] : ((t < 6) ? h2op[0] : co2p[0]);
        float nu0  = LNU0[t];
        float sT   = LSTR[t] * powf(273.15f / (T + 1e-12f), LTE[t]);
        float gL   = LWID[t] * (P / 101325.0f) * sqrtf(273.15f / (T + 1e-12f));
        float g    = 2.0f * 1.380649e-23f * T;
        g *= 6.02214076e23f;
        g /= (LMASS[t] + 1e-12f);
        float gD    = nu0 / 2.99792458e8f * sqrtf(g);
        float sigma = gD / 1.1774100226f;
        float inv_s = 1.0f / (sigma + 1e-12f);
        float y     = gL * inv_s;
        float amp   = conc * sT / (sigma * 1.7724538509f + 1e-12f);
        s_line[t] = make_float4(nu0, inv_s, y, amp);
    }
    if (t < 32) {
        float f0 = T / 273.15f;
        float f1 = P / 101325.0f;
        float f2 = h2op[0];
        float z = cont_b1[t]
                + f0 * cont_w1[t]
                + f1 * cont_w1[32 + t]
                + f2 * cont_w1[64 + t]
                +      cont_w1[96 + t];    // feat[3] = 1, feat[4] = 0
        float h = silu_f(z);
        s_h[t] = h;
        g_coef[64 + t] = h;
    }
    if (t == 0) {
        s_feat[0] = T / 273.15f;
        s_feat[1] = P / 101325.0f;
    }
    __syncthreads();

    if (t < 8) {
        float w = wl[t];
        float cross = 0.0f;
        #pragma unroll
        for (int l = 0; l < 10; l++) cross += voigt_line(w, s_line[l]);
        float z = cont_b2[t];
        #pragma unroll
        for (int j = 0; j < 32; j++) z += s_h[j] * cont_w2[j * N_WL + t];
        s_feat[2 + t] = cross + softplus_f(z);
    }
    __syncthreads();

    {
        float z = mix_b1[t];
        #pragma unroll
        for (int k = 0; k < 10; k++) z += s_feat[k] * mix_w1[k * 64 + t];
        s_m1[t] = silu_f(z);
    }
    __syncthreads();

    {
        float z = mix_b2[t];
        #pragma unroll
        for (int k = 0; k < 64; k++) z += s_m1[k] * mix_w2[k * 64 + t];
        g_coef[t] = silu_f(z);
    }
}

// ---------------------------------------------------------------------------
// Kernel B: cp.async double-buffered, 512 CTAs x 512 columns (2 cols/thread).
// Per-CTA row chunk = 2KB contiguous (vs 1KB before): halves the number of
// concurrent DRAM streams chip-wide to test the page-locality hypothesis.
// 16 stages x 6 rows (12KB/stage). PDL overlap with prep retained.
// ---------------------------------------------------------------------------
#define RPS 6
#define NSTG 16
#define COLS 512

__global__ void __launch_bounds__(256) main_kernel(
    const float* __restrict__ mix_w3,  const float* __restrict__ mix_b3,
    const float* __restrict__ cont_w2, const float* __restrict__ cont_b2,
    float* __restrict__ out)
{
    __shared__ float buf[2][RPS * COLS];   // 2 x 12KB
    __shared__ float s_coef[96];

    const int t  = threadIdx.x;
    const int c0 = blockIdx.x * COLS;

    auto issue_stage = [&](int s, int b) {
        const uint32_t base = smem_u32(&buf[b][0]);
        #pragma unroll
        for (int k = 0; k < 3; k++) {
            int idx = t + 256 * k;        // 0..767
            int ris = idx >> 7;           // row-in-stage 0..5
            int cg  = idx & 127;          // 16B group within the 2KB row chunk
            int r   = s * RPS + ris;
            const float* src = (r < 64 ? mix_w3 + r * N_WL
                                       : cont_w2 + (r - 64) * N_WL) + c0 + cg * 4;
            cp_async16(base + (uint32_t)(ris * 2048 + cg * 16), src);
        }
        asm volatile("cp.async.commit_group;" ::: "memory");
    };

    // Independent of prep's output: start the memory pipeline immediately.
    issue_stage(0, 0);
    issue_stage(1, 1);
    float b3v0 = __ldg(mix_b3 + c0 + t);
    float b3v1 = __ldg(mix_b3 + c0 + t + 256);
    float cbv0 = __ldg(cont_b2 + c0 + t);
    float cbv1 = __ldg(cont_b2 + c0 + t + 256);

    // Wait for prep's g_coef writes.
    cudaGridDependencySynchronize();
    if (t < 96) s_coef[t] = g_coef[t];

    float am0 = 0.0f, am1 = 0.0f, ac0 = 0.0f, ac1 = 0.0f;

    #pragma unroll
    for (int s = 0; s < NSTG; s++) {
        if (s < NSTG - 1) asm volatile("cp.async.wait_group 1;" ::: "memory");
        else              asm volatile("cp.async.wait_group 0;" ::: "memory");
        __syncthreads();      // stage s visible (+ s_coef on first pass)

        const float* B = buf[s & 1];
        #pragma unroll
        for (int i = 0; i < RPS; i++) {
            int r = s * RPS + i;
            float v0 = B[i * COLS + t];
            float v1 = B[i * COLS + t + 256];
            float c  = s_coef[r];
            if (r < 64) { am0 = fmaf(c, v0, am0); am1 = fmaf(c, v1, am1); }
            else        { ac0 = fmaf(c, v0, ac0); ac1 = fmaf(c, v1, ac1); }
        }
        __syncthreads();      // buffer s&1 fully consumed

        if (s + 2 < NSTG) issue_stage(s + 2, s & 1);
    }

    float zm0 = am0 + b3v0, zc0 = ac0 + cbv0;
    float zm1 = am1 + b3v1, zc1 = ac1 + cbv1;

    float e0  = __expf(-fabsf(zc0));
    float sp0 = fmaxf(zc0, 0.0f) + __logf(1.0f + e0);
    float th0 = tanh_approx(zm0 * 0.5f);
    out[c0 + t] = sp0 * fmaf(0.05f, th0, 1.0f);

    float e1  = __expf(-fabsf(zc1));
    float sp1 = fmaxf(zc1, 0.0f) + __logf(1.0f + e1);
    float th1 = tanh_approx(zm1 * 0.5f);
    out[c0 + t + 256] = sp1 * fmaf(0.05f, th1, 1.0f);
}

// ---------------------------------------------------------------------------
extern "C" void kernel_launch(void* const* d_in, const int* in_sizes, int n_in,
                              void* d_out, int out_size)
{
    const float* wl      = (const float*)d_in[0];
    const float* T       = (const float*)d_in[1];
    const float* P       = (const float*)d_in[2];
    const float* o3      = (const float*)d_in[3];
    const float* h2o     = (const float*)d_in[4];
    const float* co2     = (const float*)d_in[5];
    const float* mix_w1  = (const float*)d_in[6];
    const float* mix_b1  = (const float*)d_in[7];
    const float* mix_w2  = (const float*)d_in[8];
    const float* mix_b2  = (const float*)d_in[9];
    const float* mix_w3  = (const float*)d_in[10];
    const float* mix_b3  = (const float*)d_in[11];
    const float* cont_w1 = (const float*)d_in[12];
    const float* cont_b1 = (const float*)d_in[13];
    const float* cont_w2 = (const float*)d_in[14];
    const float* cont_b2 = (const float*)d_in[15];
    float* out = (float*)d_out;

    prep_kernel<<<1, 64>>>(wl, T, P, o3, h2o, co2,
                           mix_w1, mix_b1, mix_w2, mix_b2,
                           cont_w1, cont_b1, cont_w2, cont_b2);

    // PDL launch: main may begin before prep completes; device code holds the
    // dependency via cudaGridDependencySynchronize().
    cudaLaunchConfig_t cfg = {};
    cfg.gridDim  = dim3(N_WL / COLS);
    cfg.blockDim = dim3(256);
    cfg.dynamicSmemBytes = 0;
    cfg.stream = 0;
    cudaLaunchAttribute attrs[1];
    attrs[0].id = cudaLaunchAttributeProgrammaticStreamSerialization;
    attrs[0].val.programmaticStreamSerializationAllowed = 1;
    cfg.attrs = attrs;
    cfg.numAttrs = 1;
    cudaLaunchKernelEx(&cfg, main_kernel, mix_w3, mix_b3, cont_w2, cont_b2, out);
}

// round 13
// speedup vs baseline: 1.0845x; 1.0845x over previous
#include <cuda_runtime.h>
#include <cstdint>

#define N_WL 262144
#define RPS 6
#define NSTG 16
#define COLS 512

__device__ const float LNU0[10]  = {254.f, 280.f, 310.f, 940.f, 1130.f, 1380.f, 1400.f, 1600.f, 2000.f, 2700.f};
__device__ const float LSTR[10]  = {1.15e-17f, 5e-18f, 1.9e-19f, 2.5e-23f, 8.2e-24f, 1.8e-22f, 3.5e-25f, 7.8e-26f, 4.2e-24f, 1.2e-24f};
__device__ const float LWID[10]  = {2.0f, 3.0f, 2.5f, 3.0f, 2.5f, 4.0f, 3.0f, 2.5f, 4.0f, 3.5f};
__device__ const float LTE[10]   = {0.05f, 0.04f, 0.03f, 0.4f, 0.35f, 0.45f, 0.5f, 0.48f, 0.52f, 0.49f};
__device__ const float LMASS[10] = {48.f, 48.f, 48.f, 18.f, 18.f, 18.f, 44.f, 44.f, 44.f, 44.f};

// Voigt profile contribution for one line (prologue only, <=8 threads/CTA).
__device__ __forceinline__ float voigt_line(float wl, float4 L) {
    float x  = (wl - L.x) * L.y;
    float y  = L.z;
    float ax = fabsf(x);
    float s  = ax + y;
    float w;
    if (s >= 15.0f) {
        float t2r = y * y - x * x;
        float t2i = -2.0f * x * y;
        float dr  = 0.5f + t2r;
        float di  = t2i;
        float nr  = 0.5641896f * y;
        float ni  = 0.5641896f * (-x);
        w = (nr * dr + ni * di) / (dr * dr + di * di);
    } else if (ax >= 5.5f) {
        float tr = y, ti = -x;
        float ur = y * y - x * x;
        float ui = -2.0f * x * y;
        float ar = 1.410474f + 0.5641896f * ur;
        float ai = 0.5641896f * ui;
        float nr = tr * ar - ti * ai;
        float ni = tr * ai + ti * ar;
        float u2r = ur * ur - ui * ui;
        float u2i = 2.0f * ur * ui;
        float dr = 0.75f + 3.0f * ur + u2r;
        float di = 3.0f * ui + u2i;
        w = (nr * dr + ni * di) / (dr * dr + di * di);
    } else {
        float xx = x * x;
        w = expf(-xx) * cosf(2.0f * x * y) * 0.5641896f
          + (2.0f * y / 3.14159265358979f) * sinf(xx) / (xx + y * y + 1e-10f);
    }
    return L.w * w;
}

__device__ __forceinline__ float softplus_f(float z) {
    return fmaxf(z, 0.0f) + log1pf(expf(-fabsf(z)));
}
__device__ __forceinline__ float silu_f(float z) {
    return z / (1.0f + expf(-z));
}
__device__ __forceinline__ float tanh_approx(float z) {
    float r;
    asm("tanh.approx.f32 %0, %1;" : "=f"(r) : "f"(z));
    return r;
}

__device__ __forceinline__ uint32_t smem_u32(const void* p) {
    uint32_t a;
    asm("{ .reg .u64 t; cvta.to.shared.u64 t, %1; cvt.u32.u64 %0, t; }" : "=r"(a) : "l"(p));
    return a;
}
__device__ __forceinline__ void cp_async16(uint32_t dst, const void* src) {
    asm volatile("cp.async.cg.shared.global [%0], [%1], 16;" :: "r"(dst), "l"(src) : "memory");
}

// ---------------------------------------------------------------------------
// SINGLE fused kernel. 512 CTAs x 256 threads, 512 columns/CTA (2/thread),
// 2KB contiguous chunks per (CTA,row) stream — the R12 memory config.
// The tiny "prep" network (h, cross[:8], m1, m2) is computed redundantly per
// CTA in the shadow of the first two cp.async stages; no second launch, no
// global round-trip.
// ---------------------------------------------------------------------------
__global__ void __launch_bounds__(256) fused_kernel(
    const float* __restrict__ wl,
    const float* __restrict__ Tp,  const float* __restrict__ Pp,
    const float* __restrict__ o3p, const float* __restrict__ h2op, const float* __restrict__ co2p,
    const float* __restrict__ mix_w1,  const float* __restrict__ mix_b1,
    const float* __restrict__ mix_w2,  const float* __restrict__ mix_b2,
    const float* __restrict__ mix_w3,  const float* __restrict__ mix_b3,
    const float* __restrict__ cont_w1, const float* __restrict__ cont_b1,
    const float* __restrict__ cont_w2, const float* __restrict__ cont_b2,
    float* __restrict__ out)
{
    __shared__ float  buf[2][RPS * COLS];   // 2 x 12KB
    __shared__ float  s_coef[96];
    __shared__ float4 s_line[10];
    __shared__ float  s_h[32];
    __shared__ float  s_feat[10];
    __shared__ float  s_m1[64];

    const int t  = threadIdx.x;
    const int c0 = blockIdx.x * COLS;

    auto issue_stage = [&](int s, int b) {
        const uint32_t base = smem_u32(&buf[b][0]);
        #pragma unroll
        for (int k = 0; k < 3; k++) {
            int idx = t + 256 * k;        // 0..767
            int ris = idx >> 7;           // row-in-stage 0..5
            int cg  = idx & 127;          // 16B group within the 2KB row chunk
            int r   = s * RPS + ris;
            const float* src = (r < 64 ? mix_w3 + r * N_WL
                                       : cont_w2 + (r - 64) * N_WL) + c0 + cg * 4;
            cp_async16(base + (uint32_t)(ris * 2048 + cg * 16), src);
        }
        asm volatile("cp.async.commit_group;" ::: "memory");
    };

    // Kick the streaming pipeline first — prep below overlaps these copies.
    issue_stage(0, 0);
    issue_stage(1, 1);
    float b3v0 = __ldg(mix_b3 + c0 + t);
    float b3v1 = __ldg(mix_b3 + c0 + t + 256);
    float cbv0 = __ldg(cont_b2 + c0 + t);
    float cbv1 = __ldg(cont_b2 + c0 + t + 256);

    // ---- inlined prep (redundant per CTA; reads ~20KB via L2 broadcast) ----
    {
        const float T = Tp[0];
        const float P = Pp[0];

        if (t < 10) {
            float conc = (t < 3) ? o3p[0] : ((t < 6) ? h2op[0] : co2p[0]);
            float nu0  = LNU0[t];
            float sT   = LSTR[t] * powf(273.15f / (T + 1e-12f), LTE[t]);
            float gL   = LWID[t] * (P / 101325.0f) * sqrtf(273.15f / (T + 1e-12f));
            float g    = 2.0f * 1.380649e-23f * T;
            g *= 6.02214076e23f;
            g /= (LMASS[t] + 1e-12f);
            float gD    = nu0 / 2.99792458e8f * sqrtf(g);
            float sigma = gD / 1.1774100226f;                 // sqrt(2 ln 2)
            float inv_s = 1.0f / (sigma + 1e-12f);
            float y     = gL * inv_s;
            float amp   = conc * sT / (sigma * 1.7724538509f + 1e-12f);
            s_line[t] = make_float4(nu0, inv_s, y, amp);
        }
        if (t < 32) {
            float f0 = T / 273.15f;
            float f1 = P / 101325.0f;
            float f2 = h2op[0];
            float z = cont_b1[t]
                    + f0 * cont_w1[t]
                    + f1 * cont_w1[32 + t]
                    + f2 * cont_w1[64 + t]
                    +      cont_w1[96 + t];    // feat[3] = 1, feat[4] = 0
            s_h[t] = silu_f(z);
        }
        if (t == 0) {
            s_feat[0] = T / 273.15f;
            s_feat[1] = P / 101325.0f;
        }
        __syncthreads();

        if (t < 8) {
            float w = wl[t];
            float cross = 0.0f;
            #pragma unroll
            for (int l = 0; l < 10; l++) cross += voigt_line(w, s_line[l]);
            float z = cont_b2[t];
            #pragma unroll
            for (int j = 0; j < 32; j++) z += s_h[j] * cont_w2[j * N_WL + t];
            s_feat[2 + t] = cross + softplus_f(z);
        }
        __syncthreads();

        if (t < 64) {
            float z = mix_b1[t];
            #pragma unroll
            for (int k = 0; k < 10; k++) z += s_feat[k] * mix_w1[k * 64 + t];
            s_m1[t] = silu_f(z);
        }
        __syncthreads();

        if (t < 64) {
            float z = mix_b2[t];
            #pragma unroll
            for (int k = 0; k < 64; k++) z += s_m1[k] * mix_w2[k * 64 + t];
            s_coef[t] = silu_f(z);
        } else if (t < 96) {
            s_coef[t] = s_h[t - 64];
        }
        // visibility of s_coef is guaranteed by the mainloop's first barrier
    }

    // ---- streaming mainloop (identical to R12) ----
    float am0 = 0.0f, am1 = 0.0f, ac0 = 0.0f, ac1 = 0.0f;

    #pragma unroll
    for (int s = 0; s < NSTG; s++) {
        if (s < NSTG - 1) asm volatile("cp.async.wait_group 1;" ::: "memory");
        else              asm volatile("cp.async.wait_group 0;" ::: "memory");
        __syncthreads();      // stage s visible (+ s_coef on first pass)

        const float* B = buf[s & 1];
        #pragma unroll
        for (int i = 0; i < RPS; i++) {
            int r = s * RPS + i;
            float v0 = B[i * COLS + t];
            float v1 = B[i * COLS + t + 256];
            float c  = s_coef[r];
            if (r < 64) { am0 = fmaf(c, v0, am0); am1 = fmaf(c, v1, am1); }
            else        { ac0 = fmaf(c, v0, ac0); ac1 = fmaf(c, v1, ac1); }
        }
        __syncthreads();      // buffer s&1 fully consumed

        if (s + 2 < NSTG) issue_stage(s + 2, s & 1);
    }

    float zm0 = am0 + b3v0, zc0 = ac0 + cbv0;
    float zm1 = am1 + b3v1, zc1 = ac1 + cbv1;

    float e0  = __expf(-fabsf(zc0));
    float sp0 = fmaxf(zc0, 0.0f) + __logf(1.0f + e0);
    float th0 = tanh_approx(zm0 * 0.5f);
    out[c0 + t] = sp0 * fmaf(0.05f, th0, 1.0f);

    float e1  = __expf(-fabsf(zc1));
    float sp1 = fmaxf(zc1, 0.0f) + __logf(1.0f + e1);
    float th1 = tanh_approx(zm1 * 0.5f);
    out[c0 + t + 256] = sp1 * fmaf(0.05f, th1, 1.0f);
}

// ---------------------------------------------------------------------------
extern "C" void kernel_launch(void* const* d_in, const int* in_sizes, int n_in,
                              void* d_out, int out_size)
{
    const float* wl      = (const float*)d_in[0];
    const float* T       = (const float*)d_in[1];
    const float* P       = (const float*)d_in[2];
    const float* o3      = (const float*)d_in[3];
    const float* h2o     = (const float*)d_in[4];
    const float* co2     = (const float*)d_in[5];
    const float* mix_w1  = (const float*)d_in[6];
    const float* mix_b1  = (const float*)d_in[7];
    const float* mix_w2  = (const float*)d_in[8];
    const float* mix_b2  = (const float*)d_in[9];
    const float* mix_w3  = (const float*)d_in[10];
    const float* mix_b3  = (const float*)d_in[11];
    const float* cont_w1 = (const float*)d_in[12];
    const float* cont_b1 = (const float*)d_in[13];
    const float* cont_w2 = (const float*)d_in[14];
    const float* cont_b2 = (const float*)d_in[15];
    float* out = (float*)d_out;

    fused_kernel<<<N_WL / COLS, 256>>>(
        wl, T, P, o3, h2o, co2,
        mix_w1, mix_b1, mix_w2, mix_b2, mix_w3, mix_b3,
        cont_w1, cont_b1, cont_w2, cont_b2, out);
}